// round 9
// baseline (speedup 1.0000x reference)
#include <cuda_runtime.h>

// shuffleAug: per-sample dihedral transform of two (B,64,128,128) fp32 tensors.
// The 5 chained gathers (flipX f0, flipY f1, swap f2, flipX f3, flipY f4)
// compose into ONE source-index map:
//   if f2 (swap):  src_i = flip_{f0^f4}(j), src_j = flip_{f1^f3}(i)
//   else:          src_i = flip_{f0^f3}(i), src_j = flip_{f1^f4}(j)
// Channels are untouched, so out1 = T(x1), out2 = T(x2) independently.
//
// FINAL (converged): each block handles one 32-row output band of one plane
// (grid 4 x B*128). Non-swap: warp-contiguous 512-byte rows, one float4 per
// lane, 4 independent loads front-batched (MLP=4), pure streaming copy.
// Swap: 4 padded 32x33 smem tiles, conflict-free scatter/gather transpose.
//
// Convergence evidence (R3-R8): six structurally different variants
// (occ 42-90%, MLP 4-8, default/.cs/.wt stores, two warp layouts, pipelined
// vs batched) all pin at 6.30-6.43 TB/s = ~80% of HBM3e spec — the mixed
// 50/50 R/W efficiency ceiling. Traffic (512 MiB) is irreducible; this
// kernel sits on the roofline (best measured: 6433 GB/s, ncu 75.2us).

#define HH 128
#define HWSZ (128 * 128)

__global__ void __launch_bounds__(256) shuffleAug_kernel(
    const float* __restrict__ x1,
    const float* __restrict__ x2,
    const int* __restrict__ fb,   // (5, B) int32
    float* __restrict__ out,
    int B)
{
    __shared__ float tile[4][32][33];

    const int plane = blockIdx.y;       // b * 128 + c
    const int b = plane >> 7;
    const int c = plane & 127;

    const int f0 = fb[0 * B + b];
    const int f1 = fb[1 * B + b];
    const int sw = fb[2 * B + b];
    const int f3 = fb[3 * B + b];
    const int f4 = fb[4 * B + b];

    const int fi = sw ? (f0 ^ f4) : (f0 ^ f3);
    const int fj = sw ? (f1 ^ f3) : (f1 ^ f4);

    const float* src;
    float* dst;
    if (c < 64) {
        src = x1 + ((size_t)b * 64 + c) * HWSZ;
        dst = out + ((size_t)b * 64 + c) * HWSZ;
    } else {
        src = x2 + ((size_t)b * 64 + (c - 64)) * HWSZ;
        dst = out + (size_t)B * 64 * HWSZ + ((size_t)b * 64 + (c - 64)) * HWSZ;
    }

    const int tid = threadIdx.x;        // 0..255
    const int i0 = blockIdx.x * 32;     // output band: rows i0..i0+31, all cols

    if (!sw) {
        // ---- no transpose: warp w, lane l -> rows i0 + w + 8k (k=0..3),
        //      cols 4l..4l+3. Each warp instruction covers one full
        //      contiguous 512 B row. ----
        const int w = tid >> 5;         // 0..7
        const int l = tid & 31;         // 0..31

        float4 v[4];
        if (!fj) {
            #pragma unroll
            for (int k = 0; k < 4; k++) {
                const int r  = i0 + w + 8 * k;
                const int sr = fi ? (HH - 1) - r : r;
                v[k] = *(const float4*)(src + (size_t)sr * HH + 4 * l);
            }
        } else {
            #pragma unroll
            for (int k = 0; k < 4; k++) {
                const int r  = i0 + w + 8 * k;
                const int sr = fi ? (HH - 1) - r : r;
                float4 t = *(const float4*)(src + (size_t)sr * HH + (HH - 4) - 4 * l);
                v[k] = make_float4(t.w, t.z, t.y, t.x);
            }
        }
        #pragma unroll
        for (int k = 0; k < 4; k++) {
            const int r = i0 + w + 8 * k;
            *(float4*)(dst + (size_t)r * HH + 4 * l) = v[k];
        }
    } else {
        // ---- transpose path: 4 smem tiles, loads front-batched ----
        const int lr = tid >> 3;        // 0..31  row within tile
        const int lg = tid & 7;         // 0..7   float4 group within row

        float4 v[4];
        const int sj0 = fj ? (HH - 32) - i0 : i0;       // source cols cover v=i
        #pragma unroll
        for (int k = 0; k < 4; k++) {
            const int j0  = 32 * k;
            const int si0 = fi ? (HH - 32) - j0 : j0;   // source rows cover u=j
            v[k] = *(const float4*)(src + (size_t)(si0 + lr) * HH + sj0 + 4 * lg);
        }
        #pragma unroll
        for (int k = 0; k < 4; k++) {
            tile[k][lr][4 * lg + 0] = v[k].x;
            tile[k][lr][4 * lg + 1] = v[k].y;
            tile[k][lr][4 * lg + 2] = v[k].z;
            tile[k][lr][4 * lg + 3] = v[k].w;
        }
        __syncthreads();

        // gather: out(i,j) <- tile row fi?31-jl:jl, col fj?31-il:il
        const int scol = fj ? 31 - lr : lr;
        const int jl0  = 4 * lg;
        const int r0   = fi ? 31 - jl0 : jl0;
        const int st   = fi ? -1 : 1;
        float* drow = dst + (size_t)(i0 + lr) * HH;
        #pragma unroll
        for (int k = 0; k < 4; k++) {
            float4 w;
            w.x = tile[k][r0         ][scol];
            w.y = tile[k][r0 + st    ][scol];
            w.z = tile[k][r0 + 2 * st][scol];
            w.w = tile[k][r0 + 3 * st][scol];
            *(float4*)(drow + 32 * k + 4 * lg) = w;
        }
    }
}

extern "C" void kernel_launch(void* const* d_in, const int* in_sizes, int n_in,
                              void* d_out, int out_size)
{
    const float* x1 = (const float*)d_in[0];
    const float* x2 = (const float*)d_in[1];
    const int* fb   = (const int*)d_in[2];
    float* out      = (float*)d_out;

    const int B = in_sizes[2] / 5;      // flip_bits is (5, B)

    dim3 block(256, 1, 1);
    dim3 grid(128 / 32, B * 128, 1);    // 4 bands x 4096 planes

    shuffleAug_kernel<<<grid, block>>>(x1, x2, fb, out, B);
}

// round 10
// speedup vs baseline: 1.0012x; 1.0012x over previous
#include <cuda_runtime.h>

// shuffleAug: per-sample dihedral transform of two (B,64,128,128) fp32 tensors.
//   if f2 (swap):  src_i = flip_{f0^f4}(j), src_j = flip_{f1^f3}(i)
//   else:          src_i = flip_{f0^f3}(i), src_j = flip_{f1^f4}(j)
// out1 = T(x1), out2 = T(x2) independently.
//
// R10: non-swap path uses 256-bit (v8.f32) global loads/stores — sm_100+
// native. Each warp memory instruction covers 1 KB contiguous; 2 chunks per
// thread (64 B in flight, same as before). Swap path = proven conflict-free
// 32x33 smem tile transpose. R3-R9 pinned at the ~6.35 TB/s HBM mixed-R/W
// ceiling; this is the final burst-width probe.

#define HH 128
#define HWSZ (128 * 128)

struct f8 { float4 a, b; };

__device__ __forceinline__ f8 ldg256(const float* p) {
    f8 v;
    asm volatile("ld.global.v8.f32 {%0,%1,%2,%3,%4,%5,%6,%7}, [%8];"
        : "=f"(v.a.x), "=f"(v.a.y), "=f"(v.a.z), "=f"(v.a.w),
          "=f"(v.b.x), "=f"(v.b.y), "=f"(v.b.z), "=f"(v.b.w)
        : "l"(p));
    return v;
}

__device__ __forceinline__ void stg256(float* p, const f8& v) {
    asm volatile("st.global.v8.f32 [%0], {%1,%2,%3,%4,%5,%6,%7,%8};"
        :: "l"(p),
           "f"(v.a.x), "f"(v.a.y), "f"(v.a.z), "f"(v.a.w),
           "f"(v.b.x), "f"(v.b.y), "f"(v.b.z), "f"(v.b.w)
        : "memory");
}

__global__ void __launch_bounds__(256) shuffleAug_kernel(
    const float* __restrict__ x1,
    const float* __restrict__ x2,
    const int* __restrict__ fb,   // (5, B) int32
    float* __restrict__ out,
    int B)
{
    __shared__ float tile[4][32][33];

    const int plane = blockIdx.y;       // b * 128 + c
    const int b = plane >> 7;
    const int c = plane & 127;

    const int f0 = fb[0 * B + b];
    const int f1 = fb[1 * B + b];
    const int sw = fb[2 * B + b];
    const int f3 = fb[3 * B + b];
    const int f4 = fb[4 * B + b];

    const int fi = sw ? (f0 ^ f4) : (f0 ^ f3);
    const int fj = sw ? (f1 ^ f3) : (f1 ^ f4);

    const float* src;
    float* dst;
    if (c < 64) {
        src = x1 + ((size_t)b * 64 + c) * HWSZ;
        dst = out + ((size_t)b * 64 + c) * HWSZ;
    } else {
        src = x2 + ((size_t)b * 64 + (c - 64)) * HWSZ;
        dst = out + (size_t)B * 64 * HWSZ + ((size_t)b * 64 + (c - 64)) * HWSZ;
    }

    const int tid = threadIdx.x;        // 0..255
    const int i0 = blockIdx.x * 32;     // output band: rows i0..i0+31, all cols

    if (!sw) {
        // ---- no transpose: band = 32 rows x 16 float8-chunks = 512 chunks.
        //      Thread t handles chunks t and t+256 (2 x 32B, front-batched).
        //      Each warp instruction covers 1 KB contiguous. ----
        f8 v[2];
        int orow[2], ocol[2];
        #pragma unroll
        for (int k = 0; k < 2; k++) {
            const int ch = tid + 256 * k;       // 0..511
            const int rl = ch >> 4;             // 0..31 row within band
            const int c8 = ch & 15;             // 0..15 chunk within row
            orow[k] = i0 + rl;
            ocol[k] = 8 * c8;
            const int sr = fi ? (HH - 1) - orow[k] : orow[k];
            const int sc = fj ? (HH - 8) - ocol[k] : ocol[k];
            v[k] = ldg256(src + (size_t)sr * HH + sc);
        }
        if (fj) {
            #pragma unroll
            for (int k = 0; k < 2; k++) {
                f8 t = v[k];
                v[k].a = make_float4(t.b.w, t.b.z, t.b.y, t.b.x);
                v[k].b = make_float4(t.a.w, t.a.z, t.a.y, t.a.x);
            }
        }
        #pragma unroll
        for (int k = 0; k < 2; k++)
            stg256(dst + (size_t)orow[k] * HH + ocol[k], v[k]);
    } else {
        // ---- transpose path: 4 smem tiles, loads front-batched ----
        const int lr = tid >> 3;        // 0..31  row within tile
        const int lg = tid & 7;         // 0..7   float4 group within row

        float4 v[4];
        const int sj0 = fj ? (HH - 32) - i0 : i0;       // source cols cover v=i
        #pragma unroll
        for (int k = 0; k < 4; k++) {
            const int j0  = 32 * k;
            const int si0 = fi ? (HH - 32) - j0 : j0;   // source rows cover u=j
            v[k] = *(const float4*)(src + (size_t)(si0 + lr) * HH + sj0 + 4 * lg);
        }
        #pragma unroll
        for (int k = 0; k < 4; k++) {
            tile[k][lr][4 * lg + 0] = v[k].x;
            tile[k][lr][4 * lg + 1] = v[k].y;
            tile[k][lr][4 * lg + 2] = v[k].z;
            tile[k][lr][4 * lg + 3] = v[k].w;
        }
        __syncthreads();

        // gather: out(i,j) <- tile row fi?31-jl:jl, col fj?31-il:il
        const int scol = fj ? 31 - lr : lr;
        const int jl0  = 4 * lg;
        const int r0   = fi ? 31 - jl0 : jl0;
        const int st   = fi ? -1 : 1;
        float* drow = dst + (size_t)(i0 + lr) * HH;
        #pragma unroll
        for (int k = 0; k < 4; k++) {
            float4 w;
            w.x = tile[k][r0         ][scol];
            w.y = tile[k][r0 + st    ][scol];
            w.z = tile[k][r0 + 2 * st][scol];
            w.w = tile[k][r0 + 3 * st][scol];
            *(float4*)(drow + 32 * k + 4 * lg) = w;
        }
    }
}

extern "C" void kernel_launch(void* const* d_in, const int* in_sizes, int n_in,
                              void* d_out, int out_size)
{
    const float* x1 = (const float*)d_in[0];
    const float* x2 = (const float*)d_in[1];
    const int* fb   = (const int*)d_in[2];
    float* out      = (float*)d_out;

    const int B = in_sizes[2] / 5;      // flip_bits is (5, B)

    dim3 block(256, 1, 1);
    dim3 grid(128 / 32, B * 128, 1);    // 4 bands x 4096 planes

    shuffleAug_kernel<<<grid, block>>>(x1, x2, fb, out, B);
}